// round 11
// baseline (speedup 1.0000x reference)
#include <cuda_runtime.h>
#include <math.h>

#define BN    2048
#define CIN   256
#define NHID  512
#define NF    112
#define KC    112
#define NL    50
#define MC    100
#define NOUTC 200

__device__ float g_h0[BN * NHID];
__device__ float g_h1[BN * NHID];
__device__ float g_inter[BN * NF];
__device__ float g_base[(size_t)KC * BN * NL];
__device__ __align__(16) unsigned g_cbits[BN * MC * 4];
__device__ unsigned g_keys[KC * 2];

__device__ __forceinline__ void tf2x32(unsigned k0, unsigned k1,
                                       unsigned c0, unsigned c1,
                                       unsigned& o0, unsigned& o1) {
    unsigned ks2 = 0x1BD11BDAu ^ k0 ^ k1;
    unsigned x0 = c0 + k0, x1 = c1 + k1;
#define TF_R(r) { x0 += x1; x1 = (x1 << (r)) | (x1 >> (32 - (r))); x1 ^= x0; }
    TF_R(13) TF_R(15) TF_R(26) TF_R(6)
    x0 += k1;  x1 += ks2 + 1u;
    TF_R(17) TF_R(29) TF_R(16) TF_R(24)
    x0 += ks2; x1 += k0 + 2u;
    TF_R(13) TF_R(15) TF_R(26) TF_R(6)
    x0 += k0;  x1 += k1 + 3u;
    TF_R(17) TF_R(29) TF_R(16) TF_R(24)
    x0 += k1;  x1 += ks2 + 4u;
    TF_R(13) TF_R(15) TF_R(26) TF_R(6)
    x0 += ks2; x1 += k0 + 5u;
#undef TF_R
    o0 = x0; o1 = x1;
}

__device__ __forceinline__ float jax_uniform(unsigned k0, unsigned k1, unsigned t) {
    unsigned o0, o1, bits;
    tf2x32(k0, k1, 0u, t, o0, o1); bits = o0 ^ o1;
    return __uint_as_float((bits >> 9) | 0x3F800000u) - 1.0f;
}

__global__ void init_kernel() {
    if (blockIdx.x == 0 && threadIdx.x == 0) {
        unsigned k0 = 0u, k1 = 42u;
        for (int i = 0; i < KC; i++) {
            unsigned n0, n1, s0, s1;
            tf2x32(k0, k1, 0u, 0u, n0, n1);
            tf2x32(k0, k1, 0u, 1u, s0, s1);
            g_keys[2 * i] = s0; g_keys[2 * i + 1] = s1;
            k0 = n0; k1 = n1;
        }
    }
}

__global__ void __launch_bounds__(256) sgemm_v2(
    const float* __restrict__ A, const float* __restrict__ Bm,
    const float* __restrict__ bias, float* __restrict__ C,
    int M, int N, int Kd, int act,
    long sB, long sBias, long sC)
{
    Bm   += (size_t)blockIdx.z * sB;
    bias += (size_t)blockIdx.z * sBias;
    C    += (size_t)blockIdx.z * sC;

    __shared__ __align__(16) float As[2][16][68];
    __shared__ __align__(16) float Bs[2][16][68];
    const int bm = blockIdx.y * 64;
    const int bn = blockIdx.x * 64;
    const int tid = threadIdx.x;
    const int tr = tid / 16, tc = tid % 16;

    float acc[4][4];
#pragma unroll
    for (int i = 0; i < 4; i++)
#pragma unroll
        for (int j = 0; j < 4; j++) acc[i][j] = 0.f;

    const int nk = Kd / 16;
#pragma unroll
    for (int u = 0; u < 4; u++) {
        int l = tid + 256 * u; int m = l >> 4, k = l & 15;
        As[0][k][m] = A[(size_t)(bm + m) * Kd + k];
    }
#pragma unroll
    for (int u = 0; u < 4; u++) {
        int l = tid + 256 * u; int k = l >> 6, n = l & 63;
        Bs[0][k][n] = (bn + n < N) ? Bm[(size_t)k * N + bn + n] : 0.f;
    }
    __syncthreads();

    for (int t = 0; t < nk; t++) {
        const int cur = t & 1, nxt = cur ^ 1;
        float ra[4], rb[4];
        if (t + 1 < nk) {
            const int k0n = (t + 1) * 16;
#pragma unroll
            for (int u = 0; u < 4; u++) {
                int l = tid + 256 * u; int m = l >> 4, k = l & 15;
                ra[u] = A[(size_t)(bm + m) * Kd + k0n + k];
            }
#pragma unroll
            for (int u = 0; u < 4; u++) {
                int l = tid + 256 * u; int k = l >> 6, n = l & 63;
                rb[u] = (bn + n < N) ? Bm[(size_t)(k0n + k) * N + bn + n] : 0.f;
            }
        }
#pragma unroll
        for (int k = 0; k < 16; k++) {
            const float4 a4 = *(const float4*)&As[cur][k][tr * 4];
            const float4 b4 = *(const float4*)&Bs[cur][k][tc * 4];
            float a[4] = {a4.x, a4.y, a4.z, a4.w};
            float b[4] = {b4.x, b4.y, b4.z, b4.w};
#pragma unroll
            for (int i = 0; i < 4; i++)
#pragma unroll
                for (int j = 0; j < 4; j++)
                    acc[i][j] = fmaf(a[i], b[j], acc[i][j]);
        }
        if (t + 1 < nk) {
#pragma unroll
            for (int u = 0; u < 4; u++) {
                int l = tid + 256 * u; int m = l >> 4, k = l & 15;
                As[nxt][k][m] = ra[u];
            }
#pragma unroll
            for (int u = 0; u < 4; u++) {
                int l = tid + 256 * u; int k = l >> 6, n = l & 63;
                Bs[nxt][k][n] = rb[u];
            }
        }
        __syncthreads();
    }
#pragma unroll
    for (int i = 0; i < 4; i++) {
        int m = bm + tr * 4 + i;
#pragma unroll
        for (int j = 0; j < 4; j++) {
            int n = bn + tc * 4 + j;
            if (n < N) {
                float v = acc[i][j] + bias[n];
                if (act) v = (v > 0.f) ? v : 0.01f * v;
                C[(size_t)m * N + n] = v;
            }
        }
    }
}

__device__ __forceinline__ unsigned spread16(unsigned x) {
    x &= 0xFFFFu;
    x = (x | (x << 8)) & 0x00FF00FFu;
    x = (x | (x << 4)) & 0x0F0F0F0Fu;
    x = (x | (x << 2)) & 0x33333333u;
    x = (x | (x << 1)) & 0x55555555u;
    return x;
}

// ---------------- steps_fused v2: GEMM-style tiling (see theory) ----------------
#define HP_FLOATS (256 * 56)
#define STEPS_SMEM ((HP_FLOATS + 224 + 56 + 4) * 4 + (KC * 8 + KC * 2) * 4)
__global__ void __launch_bounds__(128) steps_fused(
    const float* __restrict__ pW1, const float* __restrict__ pW2,
    const float* __restrict__ pb2,
    float* __restrict__ c_prob, float* __restrict__ c_hard)
{
    extern __shared__ __align__(16) unsigned char dsm[];
    float*    WsHp  = (float*)dsm;                    // Ws [0,6216) / hpS [0,14336) time-disjoint
    float*    baseS = WsHp + HP_FLOATS;               // 4 x 56
    float*    W2S   = baseS + 224;                    // 56
    float*    b2p   = W2S + 56;                       // 4
    unsigned* tbS   = (unsigned*)(b2p + 4);           // 112 x 8
    unsigned* keyS  = tbS + KC * 8;                   // 224

    const int tid = threadIdx.x;
    const int P0  = blockIdx.x * 256;
    const int b0  = P0 / MC;
    const int c   = tid % 13;
    const int g   = tid / 13;
    const bool ml = (tid < 104);

    for (int l = tid; l < KC * 2; l += 128) keyS[l] = g_keys[l];

    unsigned cb0[4] = {0u,0u,0u,0u}, cb1[4] = {0u,0u,0u,0u};

    for (int i = 0; i < KC; i++) {
        for (int l = tid; l < 4 * 56; l += 128) {
            int d = l / 56, h = l - d * 56;
            int bb = b0 + d; if (bb > BN - 1) bb = BN - 1;
            baseS[l] = (h < NL) ? g_base[((size_t)i * BN + bb) * NL + h] : 0.f;
        }
        if (tid < 56) W2S[tid] = (tid < NL) ? pW2[i * NL + tid] : 0.f;
        if (tid == 0) b2p[0] = pb2[i];
        for (int l = tid; l < i * 56; l += 128) {
            int j = l / 56, h = l - j * 56;
            WsHp[l] = (h < NL) ? pW1[((size_t)i * (NF + KC) + NF + j) * NL + h] : 0.f;
        }
        __syncthreads();

        unsigned long long hp[64];
        if (ml) {
#pragma unroll
            for (int k = 0; k < 32; k++) {
                int G = P0 + g * 32 + k;
                int db = G / MC - b0;
                ulonglong2 t = *(const ulonglong2*)&baseS[db * 56 + 4 * c];
                hp[2*k] = t.x; hp[2*k+1] = t.y;
            }
            for (int j = 0; j < i; j++) {
                ulonglong2 wv = *(const ulonglong2*)&WsHp[j * 56 + 4 * c];
                unsigned bits = tbS[j * 8 + g];
#pragma unroll
                for (int k = 0; k < 32; k++) {
                    unsigned pr = bits & (1u << k);
                    asm("{\n\t.reg .pred p;\n\tsetp.ne.u32 p, %2, 0;\n\t"
                        "@p add.rn.f32x2 %0, %0, %3;\n\t"
                        "@p add.rn.f32x2 %1, %1, %4;\n\t}"
                        : "+l"(hp[2*k]), "+l"(hp[2*k+1])
                        : "r"(pr), "l"(wv.x), "l"(wv.y));
                }
            }
        }
        __syncthreads();

        if (ml) {
#pragma unroll
            for (int k = 0; k < 32; k++) {
                ulonglong2 t; t.x = hp[2*k]; t.y = hp[2*k+1];
                *(ulonglong2*)&WsHp[(size_t)(g * 32 + k) * 56 + 4 * c] = t;
            }
        }
        __syncthreads();

        const float b2v = b2p[0];
        unsigned smp[2];
#pragma unroll
        for (int e = 0; e < 2; e++) {
            const int p = 2 * tid + e;
            const float* hr = &WsHp[(size_t)p * 56];
            float z = 0.f;
#pragma unroll
            for (int q = 0; q < 12; q++) {
                float4 v4 = *(const float4*)&hr[4 * q];
                float v;
                v = v4.x; v = (v > 0.f) ? v : 0.01f * v; z = fmaf(v, W2S[4*q+0], z);
                v = v4.y; v = (v > 0.f) ? v : 0.01f * v; z = fmaf(v, W2S[4*q+1], z);
                v = v4.z; v = (v > 0.f) ? v : 0.01f * v; z = fmaf(v, W2S[4*q+2], z);
                v = v4.w; v = (v > 0.f) ? v : 0.01f * v; z = fmaf(v, W2S[4*q+3], z);
            }
            {
                float v;
                v = hr[48]; v = (v > 0.f) ? v : 0.01f * v; z = fmaf(v, W2S[48], z);
                v = hr[49]; v = (v > 0.f) ? v : 0.01f * v; z = fmaf(v, W2S[49], z);
            }
            z += b2v;
            float pp = 1.f / (1.f + expf(-z));
            unsigned s = (jax_uniform(keyS[2*i], keyS[2*i+1], (unsigned)(P0 + p)) < pp) ? 1u : 0u;
            smp[e] = s;
            const int gb = (P0 + p) / MC, gm = (P0 + p) - gb * MC;
            const size_t o = ((size_t)gb * KC + i) * MC + gm;
            c_prob[o] = pp;
            c_hard[o] = (float)s;
        }

        {
            const int wi = i >> 5; const unsigned sh = (unsigned)(i & 31);
#pragma unroll
            for (int w = 0; w < 4; w++)
                if (w == wi) { cb0[w] |= (smp[0] << sh); cb1[w] |= (smp[1] << sh); }
        }
        {
            unsigned B0 = __ballot_sync(0xffffffffu, smp[0]);
            unsigned B1 = __ballot_sync(0xffffffffu, smp[1]);
            int lane = tid & 31, W = tid >> 5;
            if (lane == 0)
                tbS[i * 8 + 2 * W]     = spread16(B0) | (spread16(B1) << 1);
            if (lane == 16)
                tbS[i * 8 + 2 * W + 1] = spread16(B0 >> 16) | (spread16(B1 >> 16) << 1);
        }
        __syncthreads();
    }

    ((uint4*)g_cbits)[P0 + 2 * tid]     = make_uint4(cb0[0], cb0[1], cb0[2], cb0[3]);
    ((uint4*)g_cbits)[P0 + 2 * tid + 1] = make_uint4(cb1[0], cb1[1], cb1[2], cb1[3]);
}

#define HEAD_ROW 256
#define HEAD_SMEM (112 * HEAD_ROW * 4 + 400 * 4 + 8 * 128 * 8)
__global__ void __launch_bounds__(256) head_fused(
    const float* __restrict__ hW, const float* __restrict__ hb,
    float* __restrict__ yp)
{
    extern __shared__ __align__(16) float hsm[];
    float*    Wsh   = hsm;
    unsigned* bitsS = (unsigned*)(hsm + 112 * HEAD_ROW);
    unsigned long long* psum = (unsigned long long*)(bitsS + 400);

    const int b = blockIdx.x, tid = threadIdx.x;
    const int w = tid >> 5, lane = tid & 31;

    for (int l = tid; l < 112 * 50; l += 256) {
        int k = l / 50, q = l - k * 50;
        *(float4*)&Wsh[k * HEAD_ROW + 4 * q] = *(const float4*)&hW[k * 200 + 4 * q];
    }
    for (int l = tid; l < 112 * 14; l += 256) {
        int k = l / 14, q = l - k * 14;
        *(float4*)&Wsh[k * HEAD_ROW + 200 + 4 * q] = make_float4(0.f, 0.f, 0.f, 0.f);
    }
    for (int l = tid; l < 400; l += 256)
        bitsS[l] = g_cbits[(size_t)b * 400 + l];
    __syncthreads();

    unsigned long long zinit[4];
#pragma unroll
    for (int q = 0; q < 4; q++) {
        int o2 = lane + 32 * q;
        float lo = (2 * o2     < NOUTC) ? hb[2 * o2]     : -1e30f;
        float hi = (2 * o2 + 1 < NOUTC) ? hb[2 * o2 + 1] : -1e30f;
        asm("mov.b64 %0, {%1, %2};" : "=l"(zinit[q]) : "r"(__float_as_uint(lo)), "r"(__float_as_uint(hi)));
    }

    float macc[8];
#pragma unroll
    for (int q = 0; q < 8; q++) macc[q] = 0.f;

    for (int m = w; m < MC; m += 8) {
        unsigned long long z2[4];
#pragma unroll
        for (int q = 0; q < 4; q++) z2[q] = zinit[q];

#pragma unroll
        for (int wd = 0; wd < 4; wd++) {
            unsigned bits = bitsS[m * 4 + wd];
            const float* wbase = Wsh + (size_t)wd * 32 * HEAD_ROW;
            while (bits) {
                int t = __ffs(bits) - 1;
                bits &= bits - 1u;
                const unsigned long long* krow =
                    (const unsigned long long*)(wbase + (size_t)t * HEAD_ROW) + lane;
#pragma unroll
                for (int q = 0; q < 4; q++) {
                    asm("add.rn.f32x2 %0, %0, %1;" : "+l"(z2[q]) : "l"(krow[32 * q]));
                }
            }
        }

        float zz[8];
#pragma unroll
        for (int q = 0; q < 4; q++) {
            unsigned lo, hi;
            asm("mov.b64 {%0, %1}, %2;" : "=r"(lo), "=r"(hi) : "l"(z2[q]));
            zz[2 * q] = __uint_as_float(lo); zz[2 * q + 1] = __uint_as_float(hi);
        }
        float mx = zz[0];
#pragma unroll
        for (int q = 1; q < 8; q++) mx = fmaxf(mx, zz[q]);
#pragma unroll
        for (int s = 16; s; s >>= 1) mx = fmaxf(mx, __shfl_xor_sync(0xffffffffu, mx, s));
        float sum = 0.f;
#pragma unroll
        for (int q = 0; q < 8; q++) { zz[q] = expf(zz[q] - mx); sum += zz[q]; }
#pragma unroll
        for (int s = 16; s; s >>= 1) sum += __shfl_xor_sync(0xffffffffu, sum, s);
        float r = 1.f / sum;
#pragma unroll
        for (int q = 0; q < 8; q++) macc[q] = fmaf(zz[q], r, macc[q]);
    }

#pragma unroll
    for (int q = 0; q < 4; q++) {
        unsigned long long pk;
        asm("mov.b64 %0, {%1, %2};" : "=l"(pk)
            : "r"(__float_as_uint(macc[2 * q])), "r"(__float_as_uint(macc[2 * q + 1])));
        psum[w * 128 + lane + 32 * q] = pk;
    }
    __syncthreads();
    if (tid < 100) {
        float slo = 0.f, shi = 0.f;
#pragma unroll
        for (int ww = 0; ww < 8; ww++) {
            unsigned lo, hi;
            asm("mov.b64 {%0, %1}, %2;" : "=r"(lo), "=r"(hi) : "l"(psum[ww * 128 + tid]));
            slo += __uint_as_float(lo); shi += __uint_as_float(hi);
        }
        yp[(size_t)b * NOUTC + 2 * tid]     = logf(slo * (1.f / MC) + 1e-6f);
        yp[(size_t)b * NOUTC + 2 * tid + 1] = logf(shi * (1.f / MC) + 1e-6f);
    }
}

extern "C" void kernel_launch(void* const* d_in, const int* in_sizes, int n_in,
                              void* d_out, int out_size) {
    const float* x     = (const float*)d_in[0];
    const float* Win   = (const float*)d_in[1];
    const float* binp  = (const float*)d_in[2];
    const float* Wh    = (const float*)d_in[3];
    const float* bh    = (const float*)d_in[4];
    const float* Wout  = (const float*)d_in[5];
    const float* bout  = (const float*)d_in[6];
    const float* pW1   = (const float*)d_in[7];
    const float* pb1   = (const float*)d_in[8];
    const float* pW2   = (const float*)d_in[9];
    const float* pb2   = (const float*)d_in[10];
    const float* hW    = (const float*)d_in[11];
    const float* hb    = (const float*)d_in[12];

    float* out    = (float*)d_out;
    float* c_prob = out;
    float* ypred  = out + (size_t)BN * KC * MC;
    float* c_hard = ypred + (size_t)BN * NOUTC;

    float *h0, *h1, *inter, *base;
    cudaGetSymbolAddress((void**)&h0,    g_h0);
    cudaGetSymbolAddress((void**)&h1,    g_h1);
    cudaGetSymbolAddress((void**)&inter, g_inter);
    cudaGetSymbolAddress((void**)&base,  g_base);

    cudaFuncSetAttribute(head_fused,  cudaFuncAttributeMaxDynamicSharedMemorySize, HEAD_SMEM);
    cudaFuncSetAttribute(steps_fused, cudaFuncAttributeMaxDynamicSharedMemorySize, STEPS_SMEM);

    init_kernel<<<1, 32>>>();

    sgemm_v2<<<dim3(NHID/64, BN/64, 1), 256>>>(x,  Win, binp, h0, BN, NHID, CIN,  1, 0,0,0);
    sgemm_v2<<<dim3(NHID/64, BN/64, 1), 256>>>(h0, Wh + 0*NHID*NHID, bh + 0*NHID, h1, BN, NHID, NHID, 1, 0,0,0);
    sgemm_v2<<<dim3(NHID/64, BN/64, 1), 256>>>(h1, Wh + 1*NHID*NHID, bh + 1*NHID, h0, BN, NHID, NHID, 1, 0,0,0);
    sgemm_v2<<<dim3(NHID/64, BN/64, 1), 256>>>(h0, Wh + 2*NHID*NHID, bh + 2*NHID, h1, BN, NHID, NHID, 1, 0,0,0);
    sgemm_v2<<<dim3(NHID/64, BN/64, 1), 256>>>(h1, Wh + 3*NHID*NHID, bh + 3*NHID, h0, BN, NHID, NHID, 1, 0,0,0);
    sgemm_v2<<<dim3(2, BN/64, 1), 256>>>(h0, Wout, bout, inter, BN, NF, NHID, 0, 0,0,0);

    sgemm_v2<<<dim3(1, BN/64, KC), 256>>>(inter, pW1, pb1, base, BN, NL, NF, 0,
                                          (long)(NF + KC) * NL, NL, (long)BN * NL);

    steps_fused<<<(BN * MC) / 256, 128, STEPS_SMEM>>>(pW1, pW2, pb2, c_prob, c_hard);

    head_fused<<<BN, 256, HEAD_SMEM>>>(hW, hb, ypred);
}

// round 12
// speedup vs baseline: 1.4105x; 1.4105x over previous
#include <cuda_runtime.h>
#include <math.h>

#define BN    2048
#define CIN   256
#define NHID  512
#define NF    112
#define KC    112
#define NL    50
#define MC    100
#define NOUTC 200

// ---------------- scratch (device globals; no allocation) ----------------
__device__ float g_h0[BN * NHID];
__device__ float g_h1[BN * NHID];
__device__ float g_inter[BN * NF];
__device__ float g_base[(size_t)KC * BN * NL];           // 45.9 MB
__device__ __align__(16) unsigned g_cbits[BN * MC * 4];  // packed c_hard bits (for head)
__device__ unsigned g_keys[KC * 2];

// ---------------- Threefry-2x32 (matches JAX) ----------------
__device__ __forceinline__ void tf2x32(unsigned k0, unsigned k1,
                                       unsigned c0, unsigned c1,
                                       unsigned& o0, unsigned& o1) {
    unsigned ks2 = 0x1BD11BDAu ^ k0 ^ k1;
    unsigned x0 = c0 + k0, x1 = c1 + k1;
#define TF_R(r) { x0 += x1; x1 = (x1 << (r)) | (x1 >> (32 - (r))); x1 ^= x0; }
    TF_R(13) TF_R(15) TF_R(26) TF_R(6)
    x0 += k1;  x1 += ks2 + 1u;
    TF_R(17) TF_R(29) TF_R(16) TF_R(24)
    x0 += ks2; x1 += k0 + 2u;
    TF_R(13) TF_R(15) TF_R(26) TF_R(6)
    x0 += k0;  x1 += k1 + 3u;
    TF_R(17) TF_R(29) TF_R(16) TF_R(24)
    x0 += k1;  x1 += ks2 + 4u;
    TF_R(13) TF_R(15) TF_R(26) TF_R(6)
    x0 += ks2; x1 += k0 + 5u;
#undef TF_R
    o0 = x0; o1 = x1;
}

__device__ __forceinline__ float jax_uniform(unsigned k0, unsigned k1, unsigned t) {
    unsigned o0, o1, bits;
    tf2x32(k0, k1, 0u, t, o0, o1); bits = o0 ^ o1;
    return __uint_as_float((bits >> 9) | 0x3F800000u) - 1.0f;
}

// ---------------- init: derive 112 subkeys ----------------
__global__ void init_kernel() {
    if (blockIdx.x == 0 && threadIdx.x == 0) {
        unsigned k0 = 0u, k1 = 42u;            // jax.random.key(42)
        for (int i = 0; i < KC; i++) {
            unsigned n0, n1, s0, s1;
            tf2x32(k0, k1, 0u, 0u, n0, n1);    // new key
            tf2x32(k0, k1, 0u, 1u, s0, s1);    // subkey
            g_keys[2 * i] = s0; g_keys[2 * i + 1] = s1;
            k0 = n0; k1 = n1;
        }
    }
}

// ---- 64x64x16 double-buffered SGEMM, LDS.128 inner loads, exact fmaf k-order ----
__global__ void __launch_bounds__(256) sgemm_v2(
    const float* __restrict__ A, const float* __restrict__ Bm,
    const float* __restrict__ bias, float* __restrict__ C,
    int M, int N, int Kd, int act,
    long sB, long sBias, long sC)
{
    Bm   += (size_t)blockIdx.z * sB;
    bias += (size_t)blockIdx.z * sBias;
    C    += (size_t)blockIdx.z * sC;

    __shared__ __align__(16) float As[2][16][68];
    __shared__ __align__(16) float Bs[2][16][68];
    const int bm = blockIdx.y * 64;
    const int bn = blockIdx.x * 64;
    const int tid = threadIdx.x;
    const int tr = tid / 16, tc = tid % 16;

    float acc[4][4];
#pragma unroll
    for (int i = 0; i < 4; i++)
#pragma unroll
        for (int j = 0; j < 4; j++) acc[i][j] = 0.f;

    const int nk = Kd / 16;
#pragma unroll
    for (int u = 0; u < 4; u++) {
        int l = tid + 256 * u; int m = l >> 4, k = l & 15;
        As[0][k][m] = A[(size_t)(bm + m) * Kd + k];
    }
#pragma unroll
    for (int u = 0; u < 4; u++) {
        int l = tid + 256 * u; int k = l >> 6, n = l & 63;
        Bs[0][k][n] = (bn + n < N) ? Bm[(size_t)k * N + bn + n] : 0.f;
    }
    __syncthreads();

    for (int t = 0; t < nk; t++) {
        const int cur = t & 1, nxt = cur ^ 1;
        float ra[4], rb[4];
        if (t + 1 < nk) {
            const int k0n = (t + 1) * 16;
#pragma unroll
            for (int u = 0; u < 4; u++) {
                int l = tid + 256 * u; int m = l >> 4, k = l & 15;
                ra[u] = A[(size_t)(bm + m) * Kd + k0n + k];
            }
#pragma unroll
            for (int u = 0; u < 4; u++) {
                int l = tid + 256 * u; int k = l >> 6, n = l & 63;
                rb[u] = (bn + n < N) ? Bm[(size_t)(k0n + k) * N + bn + n] : 0.f;
            }
        }
#pragma unroll
        for (int k = 0; k < 16; k++) {
            const float4 a4 = *(const float4*)&As[cur][k][tr * 4];
            const float4 b4 = *(const float4*)&Bs[cur][k][tc * 4];
            float a[4] = {a4.x, a4.y, a4.z, a4.w};
            float b[4] = {b4.x, b4.y, b4.z, b4.w};
#pragma unroll
            for (int i = 0; i < 4; i++)
#pragma unroll
                for (int j = 0; j < 4; j++)
                    acc[i][j] = fmaf(a[i], b[j], acc[i][j]);
        }
        if (t + 1 < nk) {
#pragma unroll
            for (int u = 0; u < 4; u++) {
                int l = tid + 256 * u; int m = l >> 4, k = l & 15;
                As[nxt][k][m] = ra[u];
            }
#pragma unroll
            for (int u = 0; u < 4; u++) {
                int l = tid + 256 * u; int k = l >> 6, n = l & 63;
                Bs[nxt][k][n] = rb[u];
            }
        }
        __syncthreads();
    }
#pragma unroll
    for (int i = 0; i < 4; i++) {
        int m = bm + tr * 4 + i;
#pragma unroll
        for (int j = 0; j < 4; j++) {
            int n = bn + tc * 4 + j;
            if (n < N) {
                float v = acc[i][j] + bias[n];
                if (act) v = (v > 0.f) ? v : 0.01f * v;
                C[(size_t)m * N + n] = v;
            }
        }
    }
}

// ---------------- ALL 112 concept steps in ONE kernel: 1 pair/thread ----------------
// The recurrence + epilogue are the hp0-half of the R9-proven body, byte-for-byte
// the same FP op order -> bit-identical p. 256 threads/block, hp = 26 u64 = 52 regs
// (vs 104 in R9) -> ~2x warps/SM for latency hiding.
__global__ void __launch_bounds__(256) steps_fused(
    const float* __restrict__ pW1, const float* __restrict__ pW2,
    const float* __restrict__ pb2,
    float* __restrict__ c_prob, float* __restrict__ c_hard)
{
    __shared__ __align__(16) float baseS[4][52];
    __shared__ float W2S[52];
    __shared__ float b2s;
    __shared__ unsigned keyS[KC * 2];
    __shared__ __align__(16) float Ws[(KC - 1) * 52];   // up to 111 rows x 52

    const int tid  = threadIdx.x;
    const int p    = blockIdx.x * 256 + tid;            // this thread's (b,m) pair
    const int b0   = (blockIdx.x * 256) / MC;
    const int b_   = p / MC, m_ = p - b_ * MC;
    const int db   = b_ - b0;

    for (int l = tid; l < KC * 2; l += 256) keyS[l] = g_keys[l];

    unsigned cb[4] = {0u, 0u, 0u, 0u};

    for (int i = 0; i < KC; i++) {
        // ---- stage step-i data ----
        for (int l = tid; l < 4 * 52; l += 256) {
            int d = l / 52, h = l - d * 52;
            int bb = b0 + d; if (bb > BN - 1) bb = BN - 1;
            baseS[d][h] = (h < NL) ? g_base[((size_t)i * BN + bb) * NL + h] : 0.f;
        }
        if (tid < 52) W2S[tid] = (tid < NL) ? pW2[i * NL + tid] : 0.f;
        if (tid == 0) b2s = pb2[i];
        for (int l = tid; l < i * 52; l += 256) {
            int j = l / 52, h = l - j * 52;
            Ws[l] = (h < NL) ? pW1[((size_t)i * (NF + KC) + NF + j) * NL + h] : 0.f;
        }
        __syncthreads();

        // ---- recurrence (hp0-half of R9 body; exact op order) ----
        unsigned long long hp[26];
        {
            const unsigned long long* s0 = (const unsigned long long*)(&baseS[db][0]);
#pragma unroll
            for (int r = 0; r < 26; r++) hp[r] = s0[r];
        }

#pragma unroll
        for (int w = 0; w < 4; w++) {
            const int jrem = i - w * 32;
            if (jrem <= 0) break;
            const int jend = (jrem < 32) ? jrem : 32;
            unsigned bw = cb[w];
            const float* wrow = Ws + (size_t)w * 32 * 52;
            for (int j2 = 0; j2 < jend; j2++) {
                float c = (bw & 1u) ? 1.f : 0.f; bw >>= 1;
                unsigned long long cc;
                asm("mov.b64 %0, {%1, %1};" : "=l"(cc) : "r"(__float_as_uint(c)));
                const ulonglong2* wr = (const ulonglong2*)(wrow + j2 * 52);
#pragma unroll
                for (int q = 0; q < 13; q++) {
                    ulonglong2 wv = wr[q];
                    asm("fma.rn.f32x2 %0, %1, %2, %0;" : "+l"(hp[2*q  ]) : "l"(cc), "l"(wv.x));
                    asm("fma.rn.f32x2 %0, %1, %2, %0;" : "+l"(hp[2*q+1]) : "l"(cc), "l"(wv.y));
                }
            }
        }

        // ---- epilogue: leaky + dot with W2 (exact R9 order) ----
        float z = 0.f;
#pragma unroll
        for (int r = 0; r < 25; r++) {
            unsigned lo, hi;
            asm("mov.b64 {%0, %1}, %2;" : "=r"(lo), "=r"(hi) : "l"(hp[r]));
            float v = __uint_as_float(lo); v = (v > 0.f) ? v : 0.01f * v; z = fmaf(v, W2S[2*r],   z);
            v = __uint_as_float(hi);       v = (v > 0.f) ? v : 0.01f * v; z = fmaf(v, W2S[2*r+1], z);
        }
        z += b2s;
        float pp = 1.f / (1.f + expf(-z));

        unsigned s = (jax_uniform(keyS[2 * i], keyS[2 * i + 1], (unsigned)p) < pp) ? 1u : 0u;

        const size_t o = ((size_t)b_ * KC + i) * MC + m_;
        c_prob[o] = pp;
        c_hard[o] = (float)s;

        const int wi = i >> 5; const unsigned sh = (unsigned)(i & 31);
#pragma unroll
        for (int w = 0; w < 4; w++)
            if (w == wi) cb[w] |= (s << sh);

        __syncthreads();   // protect smem before next step's staging
    }

    // publish packed bits for the head
    ((uint4*)g_cbits)[p] = make_uint4(cb[0], cb[1], cb[2], cb[3]);
}

// ---------------- fused head (R8-proven) ----------------
#define HEAD_ROW 256
#define HEAD_SMEM (112 * HEAD_ROW * 4 + 400 * 4 + 8 * 128 * 8)
__global__ void __launch_bounds__(256) head_fused(
    const float* __restrict__ hW, const float* __restrict__ hb,
    float* __restrict__ yp)
{
    extern __shared__ __align__(16) float hsm[];
    float*    Wsh   = hsm;                                    // 112 x 256
    unsigned* bitsS = (unsigned*)(hsm + 112 * HEAD_ROW);      // 100 x 4
    unsigned long long* psum = (unsigned long long*)(bitsS + 400);  // 8 warps x 128

    const int b = blockIdx.x, tid = threadIdx.x;
    const int w = tid >> 5, lane = tid & 31;

    for (int l = tid; l < 112 * 50; l += 256) {
        int k = l / 50, q = l - k * 50;
        *(float4*)&Wsh[k * HEAD_ROW + 4 * q] = *(const float4*)&hW[k * 200 + 4 * q];
    }
    for (int l = tid; l < 112 * 14; l += 256) {
        int k = l / 14, q = l - k * 14;
        *(float4*)&Wsh[k * HEAD_ROW + 200 + 4 * q] = make_float4(0.f, 0.f, 0.f, 0.f);
    }
    for (int l = tid; l < 400; l += 256)
        bitsS[l] = g_cbits[(size_t)b * 400 + l];
    __syncthreads();

    unsigned long long zinit[4];
#pragma unroll
    for (int q = 0; q < 4; q++) {
        int o2 = lane + 32 * q;
        float lo = (2 * o2     < NOUTC) ? hb[2 * o2]     : -1e30f;
        float hi = (2 * o2 + 1 < NOUTC) ? hb[2 * o2 + 1] : -1e30f;
        asm("mov.b64 %0, {%1, %2};" : "=l"(zinit[q]) : "r"(__float_as_uint(lo)), "r"(__float_as_uint(hi)));
    }

    float macc[8];
#pragma unroll
    for (int q = 0; q < 8; q++) macc[q] = 0.f;

    for (int m = w; m < MC; m += 8) {
        unsigned long long z2[4];
#pragma unroll
        for (int q = 0; q < 4; q++) z2[q] = zinit[q];

#pragma unroll
        for (int wd = 0; wd < 4; wd++) {
            unsigned bits = bitsS[m * 4 + wd];
            const float* wbase = Wsh + (size_t)wd * 32 * HEAD_ROW;
            while (bits) {
                int t = __ffs(bits) - 1;
                bits &= bits - 1u;
                const unsigned long long* krow =
                    (const unsigned long long*)(wbase + (size_t)t * HEAD_ROW) + lane;
#pragma unroll
                for (int q = 0; q < 4; q++) {
                    asm("add.rn.f32x2 %0, %0, %1;" : "+l"(z2[q]) : "l"(krow[32 * q]));
                }
            }
        }

        float zz[8];
#pragma unroll
        for (int q = 0; q < 4; q++) {
            unsigned lo, hi;
            asm("mov.b64 {%0, %1}, %2;" : "=r"(lo), "=r"(hi) : "l"(z2[q]));
            zz[2 * q] = __uint_as_float(lo); zz[2 * q + 1] = __uint_as_float(hi);
        }
        float mx = zz[0];
#pragma unroll
        for (int q = 1; q < 8; q++) mx = fmaxf(mx, zz[q]);
#pragma unroll
        for (int s = 16; s; s >>= 1) mx = fmaxf(mx, __shfl_xor_sync(0xffffffffu, mx, s));
        float sum = 0.f;
#pragma unroll
        for (int q = 0; q < 8; q++) { zz[q] = expf(zz[q] - mx); sum += zz[q]; }
#pragma unroll
        for (int s = 16; s; s >>= 1) sum += __shfl_xor_sync(0xffffffffu, sum, s);
        float r = 1.f / sum;
#pragma unroll
        for (int q = 0; q < 8; q++) macc[q] = fmaf(zz[q], r, macc[q]);
    }

#pragma unroll
    for (int q = 0; q < 4; q++) {
        unsigned long long pk;
        asm("mov.b64 %0, {%1, %2};" : "=l"(pk)
            : "r"(__float_as_uint(macc[2 * q])), "r"(__float_as_uint(macc[2 * q + 1])));
        psum[w * 128 + lane + 32 * q] = pk;
    }
    __syncthreads();
    if (tid < 100) {
        float slo = 0.f, shi = 0.f;
#pragma unroll
        for (int ww = 0; ww < 8; ww++) {
            unsigned lo, hi;
            asm("mov.b64 {%0, %1}, %2;" : "=r"(lo), "=r"(hi) : "l"(psum[ww * 128 + tid]));
            slo += __uint_as_float(lo); shi += __uint_as_float(hi);
        }
        yp[(size_t)b * NOUTC + 2 * tid]     = logf(slo * (1.f / MC) + 1e-6f);
        yp[(size_t)b * NOUTC + 2 * tid + 1] = logf(shi * (1.f / MC) + 1e-6f);
    }
}

// ---------------- launch ----------------
extern "C" void kernel_launch(void* const* d_in, const int* in_sizes, int n_in,
                              void* d_out, int out_size) {
    const float* x     = (const float*)d_in[0];
    const float* Win   = (const float*)d_in[1];
    const float* binp  = (const float*)d_in[2];
    const float* Wh    = (const float*)d_in[3];
    const float* bh    = (const float*)d_in[4];
    const float* Wout  = (const float*)d_in[5];
    const float* bout  = (const float*)d_in[6];
    const float* pW1   = (const float*)d_in[7];
    const float* pb1   = (const float*)d_in[8];
    const float* pW2   = (const float*)d_in[9];
    const float* pb2   = (const float*)d_in[10];
    const float* hW    = (const float*)d_in[11];
    const float* hb    = (const float*)d_in[12];

    float* out    = (float*)d_out;
    float* c_prob = out;
    float* ypred  = out + (size_t)BN * KC * MC;
    float* c_hard = ypred + (size_t)BN * NOUTC;

    float *h0, *h1, *inter, *base;
    cudaGetSymbolAddress((void**)&h0,    g_h0);
    cudaGetSymbolAddress((void**)&h1,    g_h1);
    cudaGetSymbolAddress((void**)&inter, g_inter);
    cudaGetSymbolAddress((void**)&base,  g_base);

    cudaFuncSetAttribute(head_fused, cudaFuncAttributeMaxDynamicSharedMemorySize, HEAD_SMEM);

    init_kernel<<<1, 32>>>();

    // encoder (LDS.128 db SGEMM; identical fmaf k-order -> bit-identical inter)
    sgemm_v2<<<dim3(NHID/64, BN/64, 1), 256>>>(x,  Win, binp, h0, BN, NHID, CIN,  1, 0,0,0);
    sgemm_v2<<<dim3(NHID/64, BN/64, 1), 256>>>(h0, Wh + 0*NHID*NHID, bh + 0*NHID, h1, BN, NHID, NHID, 1, 0,0,0);
    sgemm_v2<<<dim3(NHID/64, BN/64, 1), 256>>>(h1, Wh + 1*NHID*NHID, bh + 1*NHID, h0, BN, NHID, NHID, 1, 0,0,0);
    sgemm_v2<<<dim3(NHID/64, BN/64, 1), 256>>>(h0, Wh + 2*NHID*NHID, bh + 2*NHID, h1, BN, NHID, NHID, 1, 0,0,0);
    sgemm_v2<<<dim3(NHID/64, BN/64, 1), 256>>>(h1, Wh + 3*NHID*NHID, bh + 3*NHID, h0, BN, NHID, NHID, 1, 0,0,0);
    sgemm_v2<<<dim3(2, BN/64, 1), 256>>>(h0, Wout, bout, inter, BN, NF, NHID, 0, 0,0,0);

    // all base vectors: base[i] = inter @ W1[i][:NF] + b1[i]  (batched over i)
    sgemm_v2<<<dim3(1, BN/64, KC), 256>>>(inter, pW1, pb1, base, BN, NL, NF, 0,
                                          (long)(NF + KC) * NL, NL, (long)BN * NL);

    // all 112 concept steps in one kernel (1 pair/thread, 256 threads)
    steps_fused<<<(BN * MC) / 256, 256>>>(pW1, pW2, pb2, c_prob, c_hard);

    // fused head: logits -> softmax -> mean -> log
    head_fused<<<BN, 256, HEAD_SMEM>>>(hW, hb, ypred);
}